// round 7
// baseline (speedup 1.0000x reference)
#include <cuda_runtime.h>
#include <cuda_bf16.h>
#include <cstdint>

#define BD      8
#define SD      1024
#define HD      16
#define DK      64
#define DM      1024
#define TOPK    32

// ---------------- scratch (static device globals; allocation-free) ----------------
__device__ float g_v[BD * HD * SD * DK];
__device__ float g_vsum[BD * HD * DK];

// 3-term bf16 split operands (x = t0 + t1 + t2)
__device__ unsigned short g_A0[3 * 8192 * 1024];
__device__ unsigned short g_A1[3 * 8192 * 1024];
__device__ unsigned short g_A2[3 * 8192 * 1024];
__device__ unsigned short g_B0[3 * 1024 * 1024];   // [p][n][k] (W transposed)
__device__ unsigned short g_B1[3 * 1024 * 1024];
__device__ unsigned short g_B2[3 * 1024 * 1024];

__device__ unsigned short g_q0[BD * HD * SD * DK]; // [bh][s][d]
__device__ unsigned short g_q1[BD * HD * SD * DK];
__device__ unsigned short g_q2[BD * HD * SD * DK];
__device__ unsigned short g_k0[BD * HD * SD * DK];
__device__ unsigned short g_k1[BD * HD * SD * DK];
__device__ unsigned short g_k2[BD * HD * SD * DK];

// ======================= PTX helpers (base sm_100-safe) =======================
__device__ __forceinline__ uint32_t smem_u32(const void* p) {
    uint32_t a;
    asm("{ .reg .u64 t; cvta.to.shared.u64 t, %1; cvt.u32.u64 %0, t; }" : "=r"(a) : "l"(p));
    return a;
}

__device__ __forceinline__ void ldmx4(uint32_t addr, uint32_t r[4]) {
    asm volatile("ldmatrix.sync.aligned.m8n8.x4.shared.b16 {%0,%1,%2,%3}, [%4];"
                 : "=r"(r[0]), "=r"(r[1]), "=r"(r[2]), "=r"(r[3]) : "r"(addr));
}

__device__ __forceinline__ void mma16816(float d[4], const uint32_t a[4], const uint32_t* b) {
    asm volatile("mma.sync.aligned.m16n8k16.row.col.f32.bf16.bf16.f32 "
                 "{%0,%1,%2,%3}, {%4,%5,%6,%7}, {%8,%9}, {%0,%1,%2,%3};"
                 : "+f"(d[0]), "+f"(d[1]), "+f"(d[2]), "+f"(d[3])
                 : "r"(a[0]), "r"(a[1]), "r"(a[2]), "r"(a[3]), "r"(b[0]), "r"(b[1]));
}

__device__ __forceinline__ void cp_async16(uint32_t dst, const void* src) {
    asm volatile("cp.async.cg.shared.global [%0], [%1], 16;" :: "r"(dst), "l"(src));
}
#define CP_COMMIT() asm volatile("cp.async.commit_group;" ::: "memory")
template<int N> __device__ __forceinline__ void cp_wait() {
    asm volatile("cp.async.wait_group %0;" :: "n"(N) : "memory");
}

// ======================= 3-term bf16 split =======================
__device__ __forceinline__ unsigned short bf16_rn(float x, float& rem) {
    unsigned u = __float_as_uint(x);
    unsigned h = (u + 0x7FFFu + ((u >> 16) & 1u)) & 0xFFFF0000u;
    rem = x - __uint_as_float(h);
    return (unsigned short)(h >> 16);
}
__device__ __forceinline__ void split3(float x, unsigned short& t0,
                                       unsigned short& t1, unsigned short& t2) {
    float r1, r2, r3;
    t0 = bf16_rn(x, r1);
    t1 = bf16_rn(r1, r2);
    t2 = bf16_rn(r2, r3);
}

// =====================================================================
// Conversion kernels
// =====================================================================
__global__ __launch_bounds__(256) void convert_x_kernel(
    const float* __restrict__ Xq, const float* __restrict__ Xk, const float* __restrict__ Xv)
{
    const int p = blockIdx.y;
    const float* X = (p == 0) ? Xq : (p == 1) ? Xk : Xv;
    size_t base = (size_t)p * 8192 * 1024;
    size_t idx = ((size_t)blockIdx.x * 256 + threadIdx.x) * 4;
    float4 v = *(const float4*)(X + idx);
    ushort4 a, b, c;
    split3(v.x, a.x, b.x, c.x);
    split3(v.y, a.y, b.y, c.y);
    split3(v.z, a.z, b.z, c.z);
    split3(v.w, a.w, b.w, c.w);
    *(ushort4*)(g_A0 + base + idx) = a;
    *(ushort4*)(g_A1 + base + idx) = b;
    *(ushort4*)(g_A2 + base + idx) = c;
}

__global__ void convert_w_kernel(
    const float* __restrict__ Wq, const float* __restrict__ Wk, const float* __restrict__ Wv)
{
    __shared__ float t[32][33];
    const int p = blockIdx.z;
    const float* W = (p == 0) ? Wq : (p == 1) ? Wk : Wv;
    int n = blockIdx.x * 32 + threadIdx.x;
#pragma unroll
    for (int i = 0; i < 4; i++) {
        int k = blockIdx.y * 32 + threadIdx.y + i * 8;
        t[threadIdx.y + i * 8][threadIdx.x] = W[(size_t)k * 1024 + n];
    }
    __syncthreads();
    size_t base = (size_t)p * 1024 * 1024;
#pragma unroll
    for (int i = 0; i < 4; i++) {
        int nn = blockIdx.x * 32 + threadIdx.y + i * 8;
        int kk = blockIdx.y * 32 + threadIdx.x;
        float v = t[threadIdx.x][threadIdx.y + i * 8];
        unsigned short t0, t1, t2;
        split3(v, t0, t1, t2);
        g_B0[base + (size_t)nn * 1024 + kk] = t0;
        g_B1[base + (size_t)nn * 1024 + kk] = t1;
        g_B2[base + (size_t)nn * 1024 + kk] = t2;
    }
}

// =====================================================================
// mma.sync projection GEMM: 128x128 tile, 8 warps (2m x 4n), k-chunks of 32
// 3-term / 6-pass, PER-CHUNK ACCUMULATOR DRAIN (HMMA chain <= 12 steps).
// Epilogue: q,k -> 3-term bf16 [bh][s][d]; v -> fp32.
// =====================================================================
#define P_ARR   10240                 // 128 rows * 40 elems * 2B
#define P_BUF   (6 * P_ARR)           // A0|A1|A2|B0|B1|B2
#define PROJ_SMEM (1024 + 2 * P_BUF)  // 123904

__global__ __launch_bounds__(256, 1) void proj_mma_kernel(
    const float* __restrict__ bq, const float* __restrict__ bk, const float* __restrict__ bv)
{
    extern __shared__ char sm[];
    const uint32_t sb = smem_u32(sm);
    const int tid  = threadIdx.x;
    const int w    = tid >> 5;
    const int lane = tid & 31;
    const int wm = w >> 2, wn = w & 3;

    const int mt = blockIdx.y;            // 0..191
    const int p  = mt >> 6;
    const int n0 = blockIdx.x * 128;
    const size_t arow0 = (size_t)mt * 128;
    const size_t brow0 = (size_t)p * 1024 + n0;

    const float* bias = (p == 0) ? bq : (p == 1) ? bk : bv;
    if (tid < 128) ((float*)sm)[tid] = bias[n0 + tid];

    const int lrow = tid >> 1;     // 0..127
    const int half = tid & 1;      // 16-element half of the 32-k chunk

    float tot[4][4][4];            // fp32 totals (drained per chunk)
#pragma unroll
    for (int i = 0; i < 4; i++)
#pragma unroll
        for (int j = 0; j < 4; j++)
#pragma unroll
            for (int q = 0; q < 4; q++) tot[i][j][q] = 0.0f;

    auto issue = [&](int c) {
        const uint32_t bufb = sb + 1024 + (c & 1) * P_BUF;
        const int k0 = c * 32;
        const uint32_t drow = (uint32_t)(lrow * 80 + half * 32);
        const size_t aoff = (arow0 + lrow) * 1024 + k0 + half * 16;
        const size_t boff = (brow0 + lrow) * 1024 + k0 + half * 16;
        const unsigned short* s;
        s = g_A0 + aoff; cp_async16(bufb + drow, s);             cp_async16(bufb + drow + 16, s + 8);
        s = g_A1 + aoff; cp_async16(bufb + P_ARR + drow, s);     cp_async16(bufb + P_ARR + drow + 16, s + 8);
        s = g_A2 + aoff; cp_async16(bufb + 2*P_ARR + drow, s);   cp_async16(bufb + 2*P_ARR + drow + 16, s + 8);
        s = g_B0 + boff; cp_async16(bufb + 3*P_ARR + drow, s);   cp_async16(bufb + 3*P_ARR + drow + 16, s + 8);
        s = g_B1 + boff; cp_async16(bufb + 4*P_ARR + drow, s);   cp_async16(bufb + 4*P_ARR + drow + 16, s + 8);
        s = g_B2 + boff; cp_async16(bufb + 5*P_ARR + drow, s);   cp_async16(bufb + 5*P_ARR + drow + 16, s + 8);
    };

    issue(0); CP_COMMIT();

    const uint32_t a_l = (uint32_t)((((lane >> 3) & 1) * 8 + (lane & 7)) * 80 + (lane >> 4) * 16);
    const uint32_t b_l = (uint32_t)((((lane >> 4) & 1) * 8 + (lane & 7)) * 80 + ((lane >> 3) & 1) * 16);

    for (int c = 0; c < 32; c++) {
        if (c < 31) { issue(c + 1); CP_COMMIT(); cp_wait<1>(); }
        else        { cp_wait<0>(); }
        __syncthreads();

        // chunk-local accumulators (zeroed -> short HMMA chains)
        float acc[4][4][4];
#pragma unroll
        for (int i = 0; i < 4; i++)
#pragma unroll
            for (int j = 0; j < 4; j++)
#pragma unroll
                for (int q = 0; q < 4; q++) acc[i][j][q] = 0.0f;

        const uint32_t B = sb + 1024 + (c & 1) * P_BUF;
#pragma unroll
        for (int ks = 0; ks < 2; ks++) {
            const uint32_t ko = ks * 32;
            uint32_t b0f[2][4], b1f[2][4], b2f[2][4];
#pragma unroll
            for (int f2 = 0; f2 < 2; f2++) {
                const uint32_t brow = (wn * 32 + f2 * 16) * 80 + b_l + ko;
                ldmx4(B + 3*P_ARR + brow, b0f[f2]);
                ldmx4(B + 4*P_ARR + brow, b1f[f2]);
                ldmx4(B + 5*P_ARR + brow, b2f[f2]);
            }
            uint32_t af[4][4];
            // pass group 1: A0*B0, A0*B1, A0*B2
#pragma unroll
            for (int fm = 0; fm < 4; fm++)
                ldmx4(B + (wm * 64 + fm * 16) * 80 + a_l + ko, af[fm]);
#pragma unroll
            for (int fm = 0; fm < 4; fm++)
#pragma unroll
                for (int fn = 0; fn < 4; fn++) {
                    mma16816(acc[fm][fn], af[fm], &b0f[fn >> 1][(fn & 1) * 2]);
                    mma16816(acc[fm][fn], af[fm], &b1f[fn >> 1][(fn & 1) * 2]);
                    mma16816(acc[fm][fn], af[fm], &b2f[fn >> 1][(fn & 1) * 2]);
                }
            // pass group 2: A1*B0, A1*B1
#pragma unroll
            for (int fm = 0; fm < 4; fm++)
                ldmx4(B + P_ARR + (wm * 64 + fm * 16) * 80 + a_l + ko, af[fm]);
#pragma unroll
            for (int fm = 0; fm < 4; fm++)
#pragma unroll
                for (int fn = 0; fn < 4; fn++) {
                    mma16816(acc[fm][fn], af[fm], &b0f[fn >> 1][(fn & 1) * 2]);
                    mma16816(acc[fm][fn], af[fm], &b1f[fn >> 1][(fn & 1) * 2]);
                }
            // pass group 3: A2*B0
#pragma unroll
            for (int fm = 0; fm < 4; fm++)
                ldmx4(B + 2*P_ARR + (wm * 64 + fm * 16) * 80 + a_l + ko, af[fm]);
#pragma unroll
            for (int fm = 0; fm < 4; fm++)
#pragma unroll
                for (int fn = 0; fn < 4; fn++)
                    mma16816(acc[fm][fn], af[fm], &b0f[fn >> 1][(fn & 1) * 2]);
        }

        // drain chunk partials into fp32 totals
#pragma unroll
        for (int i = 0; i < 4; i++)
#pragma unroll
            for (int j = 0; j < 4; j++)
#pragma unroll
                for (int q = 0; q < 4; q++) tot[i][j][q] += acc[i][j][q];

        __syncthreads();
    }

    // ---- epilogue ----
    const float* biasp = (const float*)sm;
    unsigned short* o0 = (p == 0) ? g_q0 : g_k0;
    unsigned short* o1 = (p == 0) ? g_q1 : g_k1;
    unsigned short* o2 = (p == 0) ? g_q2 : g_k2;

#pragma unroll
    for (int fm = 0; fm < 4; fm++) {
        const int r1 = wm * 64 + fm * 16 + (lane >> 2);
#pragma unroll
        for (int fn = 0; fn < 4; fn++) {
            const int cc = wn * 32 + fn * 8 + (lane & 3) * 2;
            const float b0 = biasp[cc], b1 = biasp[cc + 1];
            const int n = n0 + cc;
            const int h = n >> 6, d = n & 63;
#pragma unroll
            for (int rr = 0; rr < 2; rr++) {
                const int ml = (mt & 63) * 128 + r1 + rr * 8;
                const int bb = ml >> 10, s = ml & 1023;
                const size_t idx = (((size_t)(bb * HD + h) * SD + s) * DK + d);
                const float v0 = tot[fm][fn][rr * 2 + 0] + b0;
                const float v1 = tot[fm][fn][rr * 2 + 1] + b1;
                if (p == 2) {
                    *(float2*)(g_v + idx) = make_float2(v0, v1);
                } else {
                    unsigned short x0, x1, x2, y0, y1, y2;
                    split3(v0, x0, x1, x2);
                    split3(v1, y0, y1, y2);
                    *(uint32_t*)(o0 + idx) = (uint32_t)x0 | ((uint32_t)y0 << 16);
                    *(uint32_t*)(o1 + idx) = (uint32_t)x1 | ((uint32_t)y1 << 16);
                    *(uint32_t*)(o2 + idx) = (uint32_t)x2 | ((uint32_t)y2 << 16);
                }
            }
        }
    }
}

// =====================================================================
// Kernel: Vsum[bh][d] = sum_s v[bh][s][d]
// =====================================================================
__global__ __launch_bounds__(256) void vsum_kernel()
{
    __shared__ float red[4][64];
    const int bh = blockIdx.x;
    const int d  = threadIdx.x & 63;
    const int c  = threadIdx.x >> 6;
    const float* vp = g_v + (size_t)bh * SD * DK + (size_t)c * 256 * DK + d;
    float s = 0.0f;
#pragma unroll 8
    for (int i = 0; i < 256; i++) s += vp[i * DK];
    red[c][d] = s;
    __syncthreads();
    if (c == 0) g_vsum[bh * DK + d] = red[0][d] + red[1][d] + red[2][d] + red[3][d];
}

// =====================================================================
// Attention: mma.sync scores (3-term/6-pass, per-ks drain) + top-32 + context
// block = 256 threads, 16 q rows, one (b,h)
// =====================================================================
#define A_SC   0                        // 16*1024*4 = 65536
#define A_Q0   65536                    // 16*144 = 2304 each
#define A_Q1   (A_Q0 + 2304)
#define A_Q2   (A_Q1 + 2304)
#define A_K0   (A_Q2 + 2304)            // 128*144 = 18432 each
#define A_K1   (A_K0 + 18432)
#define A_K2   (A_K1 + 18432)
#define A_TI   (A_K2 + 18432)           // 2048
#define A_TW   (A_TI + 2048)
#define ATT_SMEM_BYTES (A_TW + 2048)    // 131840

__global__ __launch_bounds__(256) void attn_kernel(float* __restrict__ out)
{
    extern __shared__ char smc[];
    const uint32_t sb = smem_u32(smc);

    const int bh  = blockIdx.y;
    const int q0  = blockIdx.x * 16;
    const int tid = threadIdx.x;
    const int w   = tid >> 5;
    const int lane = tid & 31;

    // ---- load q tile 3-term: [16][64] -> [16][72] padded ----
    for (int t = tid; t < 384; t += 256) {
        const int arr = t >> 7;
        const int row = (t & 127) >> 3;
        const int grp = t & 7;
        const unsigned short* src = ((arr == 0) ? g_q0 : (arr == 1) ? g_q1 : g_q2)
                                    + ((size_t)bh * SD + q0 + row) * DK + grp * 8;
        *(uint4*)(smc + A_Q0 + arr * 2304 + row * 144 + grp * 16) = *(const uint4*)src;
    }

    const uint32_t a_l = (uint32_t)((((lane >> 3) & 1) * 8 + (lane & 7)) * 144 + (lane >> 4) * 16);
    const uint32_t b_l = (uint32_t)((((lane >> 4) & 1) * 8 + (lane & 7)) * 144 + ((lane >> 3) & 1) * 16);

    const int lrow = tid >> 1;
    const int half = tid & 1;

    // ---- Phase 1: scores[16][1024] via mma.sync, 8 chunks of 128 k-rows ----
    for (int ch = 0; ch < 8; ch++) {
        __syncthreads();
        {
            const size_t kb = ((size_t)bh * SD + ch * 128 + lrow) * DK + half * 32;
            const int db = lrow * 144 + half * 64;
#pragma unroll
            for (int j = 0; j < 4; j++)
                *(uint4*)(smc + A_K0 + db + j * 16) = *(const uint4*)(g_k0 + kb + j * 8);
#pragma unroll
            for (int j = 0; j < 4; j++)
                *(uint4*)(smc + A_K1 + db + j * 16) = *(const uint4*)(g_k1 + kb + j * 8);
#pragma unroll
            for (int j = 0; j < 4; j++)
                *(uint4*)(smc + A_K2 + db + j * 16) = *(const uint4*)(g_k2 + kb + j * 8);
        }
        __syncthreads();

        float tot[2][4];
#pragma unroll
        for (int f = 0; f < 2; f++)
#pragma unroll
            for (int q = 0; q < 4; q++) tot[f][q] = 0.0f;

#pragma unroll
        for (int ks = 0; ks < 4; ks++) {
            const uint32_t ko = ks * 32;
            uint32_t q0f[4], q1f[4], q2f[4], k0f[4], k1f[4], k2f[4];
            ldmx4(sb + A_Q0 + a_l + ko, q0f);
            ldmx4(sb + A_Q1 + a_l + ko, q1f);
            ldmx4(sb + A_Q2 + a_l + ko, q2f);
            const uint32_t krow = (w * 16) * 144 + b_l + ko;
            ldmx4(sb + A_K0 + krow, k0f);
            ldmx4(sb + A_K1 + krow, k1f);
            ldmx4(sb + A_K2 + krow, k2f);

            float acc[2][4];   // ks-local accumulators (6-step HMMA chain)
#pragma unroll
            for (int f = 0; f < 2; f++)
#pragma unroll
                for (int q = 0; q < 4; q++) acc[f][q] = 0.0f;
#pragma unroll
            for (int fn = 0; fn < 2; fn++) {
                mma16816(acc[fn], q0f, &k0f[fn * 2]);
                mma16816(acc[fn], q0f, &k1f[fn * 2]);
                mma16816(acc[fn], q1f, &k0f[fn * 2]);
                mma16816(acc[fn], q0f, &k2f[fn * 2]);
                mma16816(acc[fn], q2f, &k0f[fn * 2]);
                mma16816(acc[fn], q1f, &k1f[fn * 2]);
            }
#pragma unroll
            for (int f = 0; f < 2; f++)
#pragma unroll
                for (int q = 0; q < 4; q++) tot[f][q] += acc[f][q];
        }
#pragma unroll
        for (int fn = 0; fn < 2; fn++) {
            const int col = ch * 128 + w * 16 + fn * 8 + (lane & 3) * 2;
            const int r1 = lane >> 2;
            *(float2*)(smc + A_SC + ((size_t)r1 * 1024 + col) * 4)       = make_float2(tot[fn][0], tot[fn][1]);
            *(float2*)(smc + A_SC + ((size_t)(r1 + 8) * 1024 + col) * 4) = make_float2(tot[fn][2], tot[fn][3]);
        }
    }
    __syncthreads();

    // ---- Phase 2+3: per warp, 2 rows: exact top-32 + context ----
    float (*sc)[1024]  = (float(*)[1024])(smc + A_SC);
    int   (*top_i)[32] = (int(*)[32])(smc + A_TI);
    float (*top_w)[32] = (float(*)[32])(smc + A_TW);

    const unsigned lmask_lt = (1u << lane) - 1u;
    const int bb = bh >> 4;
    const int h  = bh & 15;
    const float* vptr = g_v + (size_t)bh * SD * DK;

    for (int rr = 0; rr < 2; rr++) {
        const int row = w * 2 + rr;

        unsigned key[32];
#pragma unroll
        for (int i = 0; i < 32; i++) {
            float s = sc[row][lane + 32 * i] * 0.125f;
            unsigned ub = __float_as_uint(s);
            key[i] = (ub & 0x80000000u) ? ~ub : (ub | 0x80000000u);
        }

        unsigned T = 0u;
        bool done = false;
        for (int bit = 31; bit >= 0 && !done; --bit) {
            unsigned cand = T | (1u << bit);
            int c = 0;
#pragma unroll
            for (int i = 0; i < 32; i++) c += (key[i] >= cand) ? 1 : 0;
#pragma unroll
            for (int o = 16; o > 0; o >>= 1) c += __shfl_xor_sync(0xffffffffu, c, o);
            if (c >= TOPK) { T = cand; if (c == TOPK) done = true; }
        }

        int base = 0;
#pragma unroll
        for (int i = 0; i < 32; i++) {
            bool sel = key[i] > T;
            unsigned m = __ballot_sync(0xffffffffu, sel);
            if (sel) {
                int pos = base + __popc(m & lmask_lt);
                unsigned ub = (key[i] & 0x80000000u) ? (key[i] & 0x7fffffffu) : ~key[i];
                top_i[row][pos] = lane + 32 * i;
                top_w[row][pos] = __expf(__uint_as_float(ub));
            }
            base += __popc(m);
        }
        for (int i = 0; i < 32 && base < TOPK; i++) {
            bool sel = (key[i] == T);
            unsigned m = __ballot_sync(0xffffffffu, sel);
            if (sel) {
                int pos = base + __popc(m & lmask_lt);
                if (pos < TOPK) {
                    unsigned ub = (key[i] & 0x80000000u) ? (key[i] & 0x7fffffffu) : ~key[i];
                    top_i[row][pos] = lane + 32 * i;
                    top_w[row][pos] = __expf(__uint_as_float(ub));
                }
            }
            base += __popc(m);
        }
        __syncwarp();

        float wsum = top_w[row][lane];
#pragma unroll
        for (int o = 16; o > 0; o >>= 1) wsum += __shfl_xor_sync(0xffffffffu, wsum, o);
        float rden = 1.0f / ((float)(SD - TOPK) + wsum + 1e-8f);

        float a0 = g_vsum[bh * DK + lane * 2];
        float a1 = g_vsum[bh * DK + lane * 2 + 1];
#pragma unroll
        for (int t = 0; t < TOPK; t++) {
            int   idx = top_i[row][t];
            float wv  = top_w[row][t] - 1.0f;
            float2 vv = *(const float2*)(vptr + (size_t)idx * DK + lane * 2);
            a0 = fmaf(wv, vv.x, a0);
            a1 = fmaf(wv, vv.y, a1);
        }
        const int s_glob = q0 + row;
        *(float2*)(out + ((size_t)(bb * SD + s_glob) * DM) + h * DK + lane * 2)
            = make_float2(a0 * rden, a1 * rden);
    }
}

// =====================================================================
extern "C" void kernel_launch(void* const* d_in, const int* in_sizes, int n_in,
                              void* d_out, int out_size)
{
    (void)in_sizes; (void)n_in; (void)out_size;
    const float* Q  = (const float*)d_in[0];
    const float* K  = (const float*)d_in[1];
    const float* V  = (const float*)d_in[2];
    const float* Wq = (const float*)d_in[3];
    const float* bq = (const float*)d_in[4];
    const float* Wk = (const float*)d_in[5];
    const float* bk = (const float*)d_in[6];
    const float* Wv = (const float*)d_in[7];
    const float* bv = (const float*)d_in[8];
    float* out = (float*)d_out;

    cudaFuncSetAttribute(proj_mma_kernel, cudaFuncAttributeMaxDynamicSharedMemorySize, PROJ_SMEM);
    cudaFuncSetAttribute(attn_kernel, cudaFuncAttributeMaxDynamicSharedMemorySize, ATT_SMEM_BYTES);

    convert_x_kernel<<<dim3(8192, 3), 256>>>(Q, K, V);
    convert_w_kernel<<<dim3(32, 32, 3), dim3(32, 8)>>>(Wq, Wk, Wv);
    proj_mma_kernel<<<dim3(8, 192), 256, PROJ_SMEM>>>(bq, bk, bv);
    vsum_kernel<<<BD * HD, 256>>>();
    attn_kernel<<<dim3(SD / 16, BD * HD), 256, ATT_SMEM_BYTES>>>(out);
}

// round 9
// speedup vs baseline: 1.8990x; 1.8990x over previous
#include <cuda_runtime.h>
#include <cuda_fp16.h>
#include <cstdint>

#define BD      8
#define SD      1024
#define HD      16
#define DK      64
#define DM      1024
#define TOPK    32

// ---------------- scratch (static device globals; allocation-free) ----------------
__device__ float g_v[BD * HD * SD * DK];
__device__ float g_vsum[BD * HD * DK];

// 2-term fp16 split operands (x = t0 + t1)
__device__ unsigned short g_A0[3 * 8192 * 1024];
__device__ unsigned short g_A1[3 * 8192 * 1024];
__device__ unsigned short g_B0[3 * 1024 * 1024];   // [p][n][k] (W transposed)
__device__ unsigned short g_B1[3 * 1024 * 1024];

__device__ unsigned short g_q0[BD * HD * SD * DK]; // [bh][s][d]
__device__ unsigned short g_q1[BD * HD * SD * DK];
__device__ unsigned short g_k0[BD * HD * SD * DK];
__device__ unsigned short g_k1[BD * HD * SD * DK];

// ======================= PTX helpers (base sm_100-safe) =======================
__device__ __forceinline__ uint32_t smem_u32(const void* p) {
    uint32_t a;
    asm("{ .reg .u64 t; cvta.to.shared.u64 t, %1; cvt.u32.u64 %0, t; }" : "=r"(a) : "l"(p));
    return a;
}

__device__ __forceinline__ void ldmx4(uint32_t addr, uint32_t r[4]) {
    asm volatile("ldmatrix.sync.aligned.m8n8.x4.shared.b16 {%0,%1,%2,%3}, [%4];"
                 : "=r"(r[0]), "=r"(r[1]), "=r"(r[2]), "=r"(r[3]) : "r"(addr));
}
__device__ __forceinline__ void ldmx2(uint32_t addr, uint32_t r[2]) {
    asm volatile("ldmatrix.sync.aligned.m8n8.x2.shared.b16 {%0,%1}, [%2];"
                 : "=r"(r[0]), "=r"(r[1]) : "r"(addr));
}

__device__ __forceinline__ void mma16816(float d[4], const uint32_t a[4], const uint32_t* b) {
    asm volatile("mma.sync.aligned.m16n8k16.row.col.f32.f16.f16.f32 "
                 "{%0,%1,%2,%3}, {%4,%5,%6,%7}, {%8,%9}, {%0,%1,%2,%3};"
                 : "+f"(d[0]), "+f"(d[1]), "+f"(d[2]), "+f"(d[3])
                 : "r"(a[0]), "r"(a[1]), "r"(a[2]), "r"(a[3]), "r"(b[0]), "r"(b[1]));
}

__device__ __forceinline__ void cp_async16(uint32_t dst, const void* src) {
    asm volatile("cp.async.cg.shared.global [%0], [%1], 16;" :: "r"(dst), "l"(src));
}
#define CP_COMMIT() asm volatile("cp.async.commit_group;" ::: "memory")
template<int N> __device__ __forceinline__ void cp_wait() {
    asm volatile("cp.async.wait_group %0;" :: "n"(N) : "memory");
}

// ======================= 2-term fp16 split =======================
__device__ __forceinline__ void split2(float x, unsigned short& t0, unsigned short& t1) {
    __half h0 = __float2half_rn(x);
    float r = x - __half2float(h0);
    __half h1 = __float2half_rn(r);
    t0 = __half_as_ushort(h0);
    t1 = __half_as_ushort(h1);
}

// =====================================================================
// Conversion kernels
// =====================================================================
__global__ __launch_bounds__(256) void convert_x_kernel(
    const float* __restrict__ Xq, const float* __restrict__ Xk, const float* __restrict__ Xv)
{
    const int p = blockIdx.y;
    const float* X = (p == 0) ? Xq : (p == 1) ? Xk : Xv;
    size_t base = (size_t)p * 8192 * 1024;
    size_t idx = ((size_t)blockIdx.x * 256 + threadIdx.x) * 4;
    float4 v = *(const float4*)(X + idx);
    ushort4 a, b;
    split2(v.x, a.x, b.x);
    split2(v.y, a.y, b.y);
    split2(v.z, a.z, b.z);
    split2(v.w, a.w, b.w);
    *(ushort4*)(g_A0 + base + idx) = a;
    *(ushort4*)(g_A1 + base + idx) = b;
}

__global__ void convert_w_kernel(
    const float* __restrict__ Wq, const float* __restrict__ Wk, const float* __restrict__ Wv)
{
    __shared__ float t[32][33];
    const int p = blockIdx.z;
    const float* W = (p == 0) ? Wq : (p == 1) ? Wk : Wv;
    int n = blockIdx.x * 32 + threadIdx.x;
#pragma unroll
    for (int i = 0; i < 4; i++) {
        int k = blockIdx.y * 32 + threadIdx.y + i * 8;
        t[threadIdx.y + i * 8][threadIdx.x] = W[(size_t)k * 1024 + n];
    }
    __syncthreads();
    size_t base = (size_t)p * 1024 * 1024;
#pragma unroll
    for (int i = 0; i < 4; i++) {
        int nn = blockIdx.x * 32 + threadIdx.y + i * 8;
        int kk = blockIdx.y * 32 + threadIdx.x;
        float v = t[threadIdx.x][threadIdx.y + i * 8];
        unsigned short t0, t1;
        split2(v, t0, t1);
        g_B0[base + (size_t)nn * 1024 + kk] = t0;
        g_B1[base + (size_t)nn * 1024 + kk] = t1;
    }
}

// =====================================================================
// mma.sync projection GEMM: 128x128 tile, 8 warps (2m x 4n), k-chunks of 32
// fp16 2-term / 3-pass, per-chunk drain (HMMA chain <= 6).
// Epilogue: q,k -> 2-term fp16 [bh][s][d]; v -> fp32.
// =====================================================================
#define P_ARR   10240                 // 128 rows * 40 elems * 2B
#define P_BUF   (4 * P_ARR)           // A0|A1|B0|B1
#define PROJ_SMEM (1024 + 2 * P_BUF)  // 82944

__global__ __launch_bounds__(256, 1) void proj_mma_kernel(
    const float* __restrict__ bq, const float* __restrict__ bk, const float* __restrict__ bv)
{
    extern __shared__ char sm[];
    const uint32_t sb = smem_u32(sm);
    const int tid  = threadIdx.x;
    const int w    = tid >> 5;
    const int lane = tid & 31;
    const int wm = w >> 2, wn = w & 3;

    const int mt = blockIdx.y;            // 0..191
    const int p  = mt >> 6;
    const int n0 = blockIdx.x * 128;
    const size_t arow0 = (size_t)mt * 128;
    const size_t brow0 = (size_t)p * 1024 + n0;

    const float* bias = (p == 0) ? bq : (p == 1) ? bk : bv;
    if (tid < 128) ((float*)sm)[tid] = bias[n0 + tid];

    const int lrow = tid >> 1;     // 0..127
    const int half = tid & 1;      // 16-element half of the 32-k chunk

    float tot[4][4][4];
#pragma unroll
    for (int i = 0; i < 4; i++)
#pragma unroll
        for (int j = 0; j < 4; j++)
#pragma unroll
            for (int q = 0; q < 4; q++) tot[i][j][q] = 0.0f;

    auto issue = [&](int c) {
        const uint32_t bufb = sb + 1024 + (c & 1) * P_BUF;
        const int k0 = c * 32;
        const uint32_t drow = (uint32_t)(lrow * 80 + half * 32);
        const size_t aoff = (arow0 + lrow) * 1024 + k0 + half * 16;
        const size_t boff = (brow0 + lrow) * 1024 + k0 + half * 16;
        const unsigned short* s;
        s = g_A0 + aoff; cp_async16(bufb + drow, s);             cp_async16(bufb + drow + 16, s + 8);
        s = g_A1 + aoff; cp_async16(bufb + P_ARR + drow, s);     cp_async16(bufb + P_ARR + drow + 16, s + 8);
        s = g_B0 + boff; cp_async16(bufb + 2*P_ARR + drow, s);   cp_async16(bufb + 2*P_ARR + drow + 16, s + 8);
        s = g_B1 + boff; cp_async16(bufb + 3*P_ARR + drow, s);   cp_async16(bufb + 3*P_ARR + drow + 16, s + 8);
    };

    issue(0); CP_COMMIT();

    const uint32_t a_l = (uint32_t)((((lane >> 3) & 1) * 8 + (lane & 7)) * 80 + (lane >> 4) * 16);
    const uint32_t b_l = (uint32_t)((((lane >> 4) & 1) * 8 + (lane & 7)) * 80 + ((lane >> 3) & 1) * 16);

    for (int c = 0; c < 32; c++) {
        if (c < 31) { issue(c + 1); CP_COMMIT(); cp_wait<1>(); }
        else        { cp_wait<0>(); }
        __syncthreads();

        float acc[4][4][4];
#pragma unroll
        for (int i = 0; i < 4; i++)
#pragma unroll
            for (int j = 0; j < 4; j++)
#pragma unroll
                for (int q = 0; q < 4; q++) acc[i][j][q] = 0.0f;

        const uint32_t B = sb + 1024 + (c & 1) * P_BUF;
#pragma unroll
        for (int ks = 0; ks < 2; ks++) {
            const uint32_t ko = ks * 32;
            uint32_t b0f[2][4], b1f[2][4];
#pragma unroll
            for (int f2 = 0; f2 < 2; f2++) {
                const uint32_t brow = (wn * 32 + f2 * 16) * 80 + b_l + ko;
                ldmx4(B + 2*P_ARR + brow, b0f[f2]);
                ldmx4(B + 3*P_ARR + brow, b1f[f2]);
            }
            uint32_t af[4][4];
            // passes: A0*B0, A0*B1
#pragma unroll
            for (int fm = 0; fm < 4; fm++)
                ldmx4(B + (wm * 64 + fm * 16) * 80 + a_l + ko, af[fm]);
#pragma unroll
            for (int fm = 0; fm < 4; fm++)
#pragma unroll
                for (int fn = 0; fn < 4; fn++) {
                    mma16816(acc[fm][fn], af[fm], &b0f[fn >> 1][(fn & 1) * 2]);
                    mma16816(acc[fm][fn], af[fm], &b1f[fn >> 1][(fn & 1) * 2]);
                }
            // pass: A1*B0
#pragma unroll
            for (int fm = 0; fm < 4; fm++)
                ldmx4(B + P_ARR + (wm * 64 + fm * 16) * 80 + a_l + ko, af[fm]);
#pragma unroll
            for (int fm = 0; fm < 4; fm++)
#pragma unroll
                for (int fn = 0; fn < 4; fn++)
                    mma16816(acc[fm][fn], af[fm], &b0f[fn >> 1][(fn & 1) * 2]);
        }

#pragma unroll
        for (int i = 0; i < 4; i++)
#pragma unroll
            for (int j = 0; j < 4; j++)
#pragma unroll
                for (int q = 0; q < 4; q++) tot[i][j][q] += acc[i][j][q];

        __syncthreads();
    }

    // ---- epilogue ----
    const float* biasp = (const float*)sm;
    unsigned short* o0 = (p == 0) ? g_q0 : g_k0;
    unsigned short* o1 = (p == 0) ? g_q1 : g_k1;

#pragma unroll
    for (int fm = 0; fm < 4; fm++) {
        const int r1 = wm * 64 + fm * 16 + (lane >> 2);
#pragma unroll
        for (int fn = 0; fn < 4; fn++) {
            const int cc = wn * 32 + fn * 8 + (lane & 3) * 2;
            const float b0 = biasp[cc], b1 = biasp[cc + 1];
            const int n = n0 + cc;
            const int h = n >> 6, d = n & 63;
#pragma unroll
            for (int rr = 0; rr < 2; rr++) {
                const int ml = (mt & 63) * 128 + r1 + rr * 8;
                const int bb = ml >> 10, s = ml & 1023;
                const size_t idx = (((size_t)(bb * HD + h) * SD + s) * DK + d);
                const float v0 = tot[fm][fn][rr * 2 + 0] + b0;
                const float v1 = tot[fm][fn][rr * 2 + 1] + b1;
                if (p == 2) {
                    *(float2*)(g_v + idx) = make_float2(v0, v1);
                } else {
                    unsigned short x0, x1, y0, y1;
                    split2(v0, x0, x1);
                    split2(v1, y0, y1);
                    *(uint32_t*)(o0 + idx) = (uint32_t)x0 | ((uint32_t)y0 << 16);
                    *(uint32_t*)(o1 + idx) = (uint32_t)x1 | ((uint32_t)y1 << 16);
                }
            }
        }
    }
}

// =====================================================================
// Kernel: Vsum[bh][d] = sum_s v[bh][s][d]
// =====================================================================
__global__ __launch_bounds__(256) void vsum_kernel()
{
    __shared__ float red[4][64];
    const int bh = blockIdx.x;
    const int d  = threadIdx.x & 63;
    const int c  = threadIdx.x >> 6;
    const float* vp = g_v + (size_t)bh * SD * DK + (size_t)c * 256 * DK + d;
    float s = 0.0f;
#pragma unroll 8
    for (int i = 0; i < 256; i++) s += vp[i * DK];
    red[c][d] = s;
    __syncthreads();
    if (c == 0) g_vsum[bh * DK + d] = red[0][d] + red[1][d] + red[2][d] + red[3][d];
}

// =====================================================================
// Attention: fp16 2-term mma.sync scores (cp.async 64-row k chunks, per-ks
// drain) + exact top-32 + context. 256 threads, 16 q rows, one (b,h).
// Target: 2 blocks/SM (smem 111104, regs capped via launch_bounds).
// =====================================================================
#define A_SC   0                        // 16*1024*4 = 65536
#define A_Q0   65536                    // 16*144 = 2304 each
#define A_Q1   (A_Q0 + 2304)
#define A_KS   (A_Q1 + 2304)            // 2 stages * 2 terms * 64*144 = 36864
#define A_TI   (A_KS + 36864)           // 2048
#define A_TW   (A_TI + 2048)
#define ATT_SMEM_BYTES (A_TW + 2048)    // 111104

__global__ __launch_bounds__(256, 2) void attn_kernel(float* __restrict__ out)
{
    extern __shared__ char smc[];
    const uint32_t sb = smem_u32(smc);

    const int bh  = blockIdx.y;
    const int q0  = blockIdx.x * 16;
    const int tid = threadIdx.x;
    const int w   = tid >> 5;
    const int lane = tid & 31;

    // ---- load q tile 2-term: [16][64] -> [16][72] padded ----
    {
        const int arr = tid >> 7;            // 0,1
        const int row = (tid & 127) >> 3;
        const int grp = tid & 7;
        const unsigned short* src = ((arr == 0) ? g_q0 : g_q1)
                                    + ((size_t)bh * SD + q0 + row) * DK + grp * 8;
        *(uint4*)(smc + A_Q0 + arr * 2304 + row * 144 + grp * 16) = *(const uint4*)src;
    }

    const uint32_t a_l = (uint32_t)((((lane >> 3) & 1) * 8 + (lane & 7)) * 144 + (lane >> 4) * 16);
    const int l16 = lane & 15;
    const uint32_t b_l2 = (uint32_t)((l16 & 7) * 144 + (l16 >> 3) * 16);

    // ---- k chunk cp.async issue: 64 rows x 128B x 2 terms ----
    const int krow = tid >> 2;     // 0..63
    const int kq   = tid & 3;
    auto kissue = [&](int ch) {
        const uint32_t dst = sb + A_KS + (ch & 1) * 18432 + (uint32_t)(krow * 144 + kq * 32);
        const size_t src = ((size_t)bh * SD + ch * 64 + krow) * DK + kq * 16;
        cp_async16(dst, g_k0 + src);           cp_async16(dst + 16, g_k0 + src + 8);
        cp_async16(dst + 9216, g_k1 + src);    cp_async16(dst + 9216 + 16, g_k1 + src + 8);
    };

    kissue(0); CP_COMMIT();
    __syncthreads();   // q tile visible

    // hoist q fragments (constant across chunks)
    uint32_t qf0[4][4], qf1[4][4];
#pragma unroll
    for (int ks = 0; ks < 4; ks++) {
        ldmx4(sb + A_Q0 + a_l + ks * 32, qf0[ks]);
        ldmx4(sb + A_Q1 + a_l + ks * 32, qf1[ks]);
    }

    // ---- Phase 1: scores[16][1024], 16 chunks of 64 k-rows ----
    for (int ch = 0; ch < 16; ch++) {
        if (ch < 15) { kissue(ch + 1); CP_COMMIT(); cp_wait<1>(); }
        else         { cp_wait<0>(); }
        __syncthreads();

        const uint32_t kbase = sb + A_KS + (ch & 1) * 18432 + (uint32_t)((w * 8) * 144);
        float tot4[4] = {0.0f, 0.0f, 0.0f, 0.0f};
#pragma unroll
        for (int ks = 0; ks < 4; ks++) {
            uint32_t k0f[2], k1f[2];
            ldmx2(kbase + b_l2 + ks * 32, k0f);
            ldmx2(kbase + 9216 + b_l2 + ks * 32, k1f);
            float acc[4] = {0.0f, 0.0f, 0.0f, 0.0f};
            mma16816(acc, qf0[ks], k0f);
            mma16816(acc, qf0[ks], k1f);
            mma16816(acc, qf1[ks], k0f);
#pragma unroll
            for (int q = 0; q < 4; q++) tot4[q] += acc[q];
        }
        {
            const int col = ch * 64 + w * 8 + (lane & 3) * 2;
            const int r1 = lane >> 2;
            *(float2*)(smc + A_SC + ((size_t)r1 * 1024 + col) * 4)       = make_float2(tot4[0], tot4[1]);
            *(float2*)(smc + A_SC + ((size_t)(r1 + 8) * 1024 + col) * 4) = make_float2(tot4[2], tot4[3]);
        }
        __syncthreads();
    }

    // ---- Phase 2+3: per warp, 2 rows: exact top-32 + context ----
    float (*sc)[1024]  = (float(*)[1024])(smc + A_SC);
    int   (*top_i)[32] = (int(*)[32])(smc + A_TI);
    float (*top_w)[32] = (float(*)[32])(smc + A_TW);

    const unsigned lmask_lt = (1u << lane) - 1u;
    const int bb = bh >> 4;
    const int h  = bh & 15;
    const float* vptr = g_v + (size_t)bh * SD * DK;

    for (int rr = 0; rr < 2; rr++) {
        const int row = w * 2 + rr;

        unsigned key[32];
#pragma unroll
        for (int i = 0; i < 32; i++) {
            float s = sc[row][lane + 32 * i] * 0.125f;
            unsigned ub = __float_as_uint(s);
            key[i] = (ub & 0x80000000u) ? ~ub : (ub | 0x80000000u);
        }

        unsigned T = 0u;
        bool done = false;
        for (int bit = 31; bit >= 0 && !done; --bit) {
            unsigned cand = T | (1u << bit);
            int c = 0;
#pragma unroll
            for (int i = 0; i < 32; i++) c += (key[i] >= cand) ? 1 : 0;
#pragma unroll
            for (int o = 16; o > 0; o >>= 1) c += __shfl_xor_sync(0xffffffffu, c, o);
            if (c >= TOPK) { T = cand; if (c == TOPK) done = true; }
        }

        int base = 0;
#pragma unroll
        for (int i = 0; i < 32; i++) {
            bool sel = key[i] > T;
            unsigned m = __ballot_sync(0xffffffffu, sel);
            if (sel) {
                int pos = base + __popc(m & lmask_lt);
                unsigned ub = (key[i] & 0x80000000u) ? (key[i] & 0x7fffffffu) : ~key[i];
                top_i[row][pos] = lane + 32 * i;
                top_w[row][pos] = __expf(__uint_as_float(ub));
            }
            base += __popc(m);
        }
        for (int i = 0; i < 32 && base < TOPK; i++) {
            bool sel = (key[i] == T);
            unsigned m = __ballot_sync(0xffffffffu, sel);
            if (sel) {
                int pos = base + __popc(m & lmask_lt);
                if (pos < TOPK) {
                    unsigned ub = (key[i] & 0x80000000u) ? (key[i] & 0x7fffffffu) : ~key[i];
                    top_i[row][pos] = lane + 32 * i;
                    top_w[row][pos] = __expf(__uint_as_float(ub));
                }
            }
            base += __popc(m);
        }
        __syncwarp();

        float wsum = top_w[row][lane];
#pragma unroll
        for (int o = 16; o > 0; o >>= 1) wsum += __shfl_xor_sync(0xffffffffu, wsum, o);
        float rden = 1.0f / ((float)(SD - TOPK) + wsum + 1e-8f);

        float a0 = g_vsum[bh * DK + lane * 2];
        float a1 = g_vsum[bh * DK + lane * 2 + 1];
#pragma unroll
        for (int t = 0; t < TOPK; t++) {
            int   idx = top_i[row][t];
            float wv  = top_w[row][t] - 1.0f;
            float2 vv = *(const float2*)(vptr + (size_t)idx * DK + lane * 2);
            a0 = fmaf(wv, vv.x, a0);
            a1 = fmaf(wv, vv.y, a1);
        }
        const int s_glob = q0 + row;
        *(float2*)(out + ((size_t)(bb * SD + s_glob) * DM) + h * DK + lane * 2)
            = make_float2(a0 * rden, a1 * rden);
    }
}

// =====================================================================
extern "C" void kernel_launch(void* const* d_in, const int* in_sizes, int n_in,
                              void* d_out, int out_size)
{
    (void)in_sizes; (void)n_in; (void)out_size;
    const float* Q  = (const float*)d_in[0];
    const float* K  = (const float*)d_in[1];
    const float* V  = (const float*)d_in[2];
    const float* Wq = (const float*)d_in[3];
    const float* bq = (const float*)d_in[4];
    const float* Wk = (const float*)d_in[5];
    const float* bk = (const float*)d_in[6];
    const float* Wv = (const float*)d_in[7];
    const float* bv = (const float*)d_in[8];
    float* out = (float*)d_out;

    cudaFuncSetAttribute(proj_mma_kernel, cudaFuncAttributeMaxDynamicSharedMemorySize, PROJ_SMEM);
    cudaFuncSetAttribute(attn_kernel, cudaFuncAttributeMaxDynamicSharedMemorySize, ATT_SMEM_BYTES);

    convert_x_kernel<<<dim3(8192, 3), 256>>>(Q, K, V);
    convert_w_kernel<<<dim3(32, 32, 3), dim3(32, 8)>>>(Wq, Wk, Wv);
    proj_mma_kernel<<<dim3(8, 192), 256, PROJ_SMEM>>>(bq, bk, bv);
    vsum_kernel<<<BD * HD, 256>>>();
    attn_kernel<<<dim3(SD / 16, BD * HD), 256, ATT_SMEM_BYTES>>>(out);
}

// round 10
// speedup vs baseline: 1.9004x; 1.0007x over previous
#include <cuda_runtime.h>
#include <cuda_fp16.h>
#include <cstdint>

#define BD      8
#define SD      1024
#define HD      16
#define DK      64
#define DM      1024
#define TOPK    32

// ---------------- scratch (static device globals; allocation-free) ----------------
__device__ float g_v[BD * HD * SD * DK];
__device__ float g_vsum[BD * HD * DK];

// 2-term fp16 split operands (x = t0 + t1)
__device__ unsigned short g_A0[3 * 8192 * 1024];
__device__ unsigned short g_A1[3 * 8192 * 1024];
__device__ unsigned short g_B0[3 * 1024 * 1024];   // [p][n][k] (W transposed)
__device__ unsigned short g_B1[3 * 1024 * 1024];

__device__ unsigned short g_q0[BD * HD * SD * DK]; // [bh][s][d]
__device__ unsigned short g_q1[BD * HD * SD * DK];
__device__ unsigned short g_k0[BD * HD * SD * DK];
__device__ unsigned short g_k1[BD * HD * SD * DK];

// ======================= PTX helpers (base sm_100-safe) =======================
__device__ __forceinline__ uint32_t smem_u32(const void* p) {
    uint32_t a;
    asm("{ .reg .u64 t; cvta.to.shared.u64 t, %1; cvt.u32.u64 %0, t; }" : "=r"(a) : "l"(p));
    return a;
}

__device__ __forceinline__ void ldmx4(uint32_t addr, uint32_t r[4]) {
    asm volatile("ldmatrix.sync.aligned.m8n8.x4.shared.b16 {%0,%1,%2,%3}, [%4];"
                 : "=r"(r[0]), "=r"(r[1]), "=r"(r[2]), "=r"(r[3]) : "r"(addr));
}
__device__ __forceinline__ void ldmx2(uint32_t addr, uint32_t r[2]) {
    asm volatile("ldmatrix.sync.aligned.m8n8.x2.shared.b16 {%0,%1}, [%2];"
                 : "=r"(r[0]), "=r"(r[1]) : "r"(addr));
}

__device__ __forceinline__ void mma16816(float d[4], const uint32_t a[4], const uint32_t* b) {
    asm volatile("mma.sync.aligned.m16n8k16.row.col.f32.f16.f16.f32 "
                 "{%0,%1,%2,%3}, {%4,%5,%6,%7}, {%8,%9}, {%0,%1,%2,%3};"
                 : "+f"(d[0]), "+f"(d[1]), "+f"(d[2]), "+f"(d[3])
                 : "r"(a[0]), "r"(a[1]), "r"(a[2]), "r"(a[3]), "r"(b[0]), "r"(b[1]));
}

// zero-init variant: d = a*b + 0 (no MOV-zero of accumulators needed)
__device__ __forceinline__ void mma16816_zi(float d[4], const uint32_t a[4], const uint32_t* b) {
    asm volatile("mma.sync.aligned.m16n8k16.row.col.f32.f16.f16.f32 "
                 "{%0,%1,%2,%3}, {%4,%5,%6,%7}, {%8,%9}, {%10,%11,%12,%13};"
                 : "=f"(d[0]), "=f"(d[1]), "=f"(d[2]), "=f"(d[3])
                 : "r"(a[0]), "r"(a[1]), "r"(a[2]), "r"(a[3]), "r"(b[0]), "r"(b[1]),
                   "f"(0.0f), "f"(0.0f), "f"(0.0f), "f"(0.0f));
}

__device__ __forceinline__ void cp_async16(uint32_t dst, const void* src) {
    asm volatile("cp.async.cg.shared.global [%0], [%1], 16;" :: "r"(dst), "l"(src));
}
#define CP_COMMIT() asm volatile("cp.async.commit_group;" ::: "memory")
template<int N> __device__ __forceinline__ void cp_wait() {
    asm volatile("cp.async.wait_group %0;" :: "n"(N) : "memory");
}

// ======================= 2-term fp16 split =======================
__device__ __forceinline__ void split2(float x, unsigned short& t0, unsigned short& t1) {
    __half h0 = __float2half_rn(x);
    float r = x - __half2float(h0);
    __half h1 = __float2half_rn(r);
    t0 = __half_as_ushort(h0);
    t1 = __half_as_ushort(h1);
}

// =====================================================================
// Merged conversion kernel: blocks [0,24576) = X split, [24576,27648) = W
// (merging shrinks the launch cycle to 4 so ncu -s 5 lands on proj/attn)
// =====================================================================
__global__ __launch_bounds__(256) void convert_all_kernel(
    const float* __restrict__ Xq, const float* __restrict__ Xk, const float* __restrict__ Xv,
    const float* __restrict__ Wq, const float* __restrict__ Wk, const float* __restrict__ Wv)
{
    __shared__ float t[32][33];
    const int b = blockIdx.x;
    const int tid = threadIdx.x;

    if (b < 24576) {
        const int p = b >> 13;             // b / 8192
        const int blk = b & 8191;
        const float* X = (p == 0) ? Xq : (p == 1) ? Xk : Xv;
        size_t base = (size_t)p * 8192 * 1024;
        size_t idx = ((size_t)blk * 256 + tid) * 4;
        float4 v = *(const float4*)(X + idx);
        ushort4 a, c;
        split2(v.x, a.x, c.x);
        split2(v.y, a.y, c.y);
        split2(v.z, a.z, c.z);
        split2(v.w, a.w, c.w);
        *(ushort4*)(g_A0 + base + idx) = a;
        *(ushort4*)(g_A1 + base + idx) = c;
    } else {
        const int wb = b - 24576;
        const int p  = wb >> 10;           // wb / 1024
        const int rem = wb & 1023;
        const int bx = rem & 31;
        const int by = rem >> 5;
        const int tx = tid & 31;
        const int ty = tid >> 5;           // 0..7
        const float* W = (p == 0) ? Wq : (p == 1) ? Wk : Wv;
        int n = bx * 32 + tx;
#pragma unroll
        for (int i = 0; i < 4; i++) {
            int k = by * 32 + ty + i * 8;
            t[ty + i * 8][tx] = W[(size_t)k * 1024 + n];
        }
        __syncthreads();
        size_t base = (size_t)p * 1024 * 1024;
#pragma unroll
        for (int i = 0; i < 4; i++) {
            int nn = bx * 32 + ty + i * 8;
            int kk = by * 32 + tx;
            float v = t[tx][ty + i * 8];
            unsigned short t0, t1;
            split2(v, t0, t1);
            g_B0[base + (size_t)nn * 1024 + kk] = t0;
            g_B1[base + (size_t)nn * 1024 + kk] = t1;
        }
    }
}

// =====================================================================
// mma.sync projection GEMM: 128x128 tile, 8 warps (2m x 4n), k-chunks of 32
// fp16 2-term / 3-pass, drain every 2 chunks (HMMA chain <= 12),
// zero-free accumulator restart via mma_zi.
// Epilogue: q,k -> 2-term fp16 [bh][s][d]; v -> fp32.
// =====================================================================
#define P_ARR   10240                 // 128 rows * 40 elems * 2B
#define P_BUF   (4 * P_ARR)           // A0|A1|B0|B1
#define PROJ_SMEM (1024 + 2 * P_BUF)  // 82944

__global__ __launch_bounds__(256, 1) void proj_mma_kernel(
    const float* __restrict__ bq, const float* __restrict__ bk, const float* __restrict__ bv)
{
    extern __shared__ char sm[];
    const uint32_t sb = smem_u32(sm);
    const int tid  = threadIdx.x;
    const int w    = tid >> 5;
    const int lane = tid & 31;
    const int wm = w >> 2, wn = w & 3;

    const int mt = blockIdx.y;            // 0..191
    const int p  = mt >> 6;
    const int n0 = blockIdx.x * 128;
    const size_t arow0 = (size_t)mt * 128;
    const size_t brow0 = (size_t)p * 1024 + n0;

    const float* bias = (p == 0) ? bq : (p == 1) ? bk : bv;
    if (tid < 128) ((float*)sm)[tid] = bias[n0 + tid];

    const int lrow = tid >> 1;     // 0..127
    const int half = tid & 1;      // 16-element half of the 32-k chunk

    float tot[4][4][4];
    float acc[4][4][4];
#pragma unroll
    for (int i = 0; i < 4; i++)
#pragma unroll
        for (int j = 0; j < 4; j++)
#pragma unroll
            for (int q = 0; q < 4; q++) tot[i][j][q] = 0.0f;

    auto issue = [&](int c) {
        const uint32_t bufb = sb + 1024 + (c & 1) * P_BUF;
        const int k0 = c * 32;
        const uint32_t drow = (uint32_t)(lrow * 80 + half * 32);
        const size_t aoff = (arow0 + lrow) * 1024 + k0 + half * 16;
        const size_t boff = (brow0 + lrow) * 1024 + k0 + half * 16;
        const unsigned short* s;
        s = g_A0 + aoff; cp_async16(bufb + drow, s);             cp_async16(bufb + drow + 16, s + 8);
        s = g_A1 + aoff; cp_async16(bufb + P_ARR + drow, s);     cp_async16(bufb + P_ARR + drow + 16, s + 8);
        s = g_B0 + boff; cp_async16(bufb + 2*P_ARR + drow, s);   cp_async16(bufb + 2*P_ARR + drow + 16, s + 8);
        s = g_B1 + boff; cp_async16(bufb + 3*P_ARR + drow, s);   cp_async16(bufb + 3*P_ARR + drow + 16, s + 8);
    };

    issue(0); CP_COMMIT();

    const uint32_t a_l = (uint32_t)((((lane >> 3) & 1) * 8 + (lane & 7)) * 80 + (lane >> 4) * 16);
    const uint32_t b_l = (uint32_t)((((lane >> 4) & 1) * 8 + (lane & 7)) * 80 + ((lane >> 3) & 1) * 16);

    for (int c = 0; c < 32; c++) {
        if (c < 31) { issue(c + 1); CP_COMMIT(); cp_wait<1>(); }
        else        { cp_wait<0>(); }
        __syncthreads();

        const bool fresh = ((c & 1) == 0);   // acc restarts on even chunks
        const uint32_t B = sb + 1024 + (c & 1) * P_BUF;
#pragma unroll
        for (int ks = 0; ks < 2; ks++) {
            const uint32_t ko = ks * 32;
            uint32_t b0f[2][4], b1f[2][4];
#pragma unroll
            for (int f2 = 0; f2 < 2; f2++) {
                const uint32_t brow = (wn * 32 + f2 * 16) * 80 + b_l + ko;
                ldmx4(B + 2*P_ARR + brow, b0f[f2]);
                ldmx4(B + 3*P_ARR + brow, b1f[f2]);
            }
            uint32_t af[4][4];
            // passes: A0*B0 (zi on restart), A0*B1
#pragma unroll
            for (int fm = 0; fm < 4; fm++)
                ldmx4(B + (wm * 64 + fm * 16) * 80 + a_l + ko, af[fm]);
            if (ks == 0 && fresh) {
#pragma unroll
                for (int fm = 0; fm < 4; fm++)
#pragma unroll
                    for (int fn = 0; fn < 4; fn++) {
                        mma16816_zi(acc[fm][fn], af[fm], &b0f[fn >> 1][(fn & 1) * 2]);
                        mma16816(acc[fm][fn], af[fm], &b1f[fn >> 1][(fn & 1) * 2]);
                    }
            } else {
#pragma unroll
                for (int fm = 0; fm < 4; fm++)
#pragma unroll
                    for (int fn = 0; fn < 4; fn++) {
                        mma16816(acc[fm][fn], af[fm], &b0f[fn >> 1][(fn & 1) * 2]);
                        mma16816(acc[fm][fn], af[fm], &b1f[fn >> 1][(fn & 1) * 2]);
                    }
            }
            // pass: A1*B0
#pragma unroll
            for (int fm = 0; fm < 4; fm++)
                ldmx4(B + P_ARR + (wm * 64 + fm * 16) * 80 + a_l + ko, af[fm]);
#pragma unroll
            for (int fm = 0; fm < 4; fm++)
#pragma unroll
                for (int fn = 0; fn < 4; fn++)
                    mma16816(acc[fm][fn], af[fm], &b0f[fn >> 1][(fn & 1) * 2]);
        }

        if (c & 1) {   // drain after odd chunks (chain <= 12 HMMA)
#pragma unroll
            for (int i = 0; i < 4; i++)
#pragma unroll
                for (int j = 0; j < 4; j++)
#pragma unroll
                    for (int q = 0; q < 4; q++) tot[i][j][q] += acc[i][j][q];
        }
        __syncthreads();
    }

    // ---- epilogue ----
    const float* biasp = (const float*)sm;
    unsigned short* o0 = (p == 0) ? g_q0 : g_k0;
    unsigned short* o1 = (p == 0) ? g_q1 : g_k1;

#pragma unroll
    for (int fm = 0; fm < 4; fm++) {
        const int r1 = wm * 64 + fm * 16 + (lane >> 2);
#pragma unroll
        for (int fn = 0; fn < 4; fn++) {
            const int cc = wn * 32 + fn * 8 + (lane & 3) * 2;
            const float b0 = biasp[cc], b1 = biasp[cc + 1];
            const int n = n0 + cc;
            const int h = n >> 6, d = n & 63;
#pragma unroll
            for (int rr = 0; rr < 2; rr++) {
                const int ml = (mt & 63) * 128 + r1 + rr * 8;
                const int bb = ml >> 10, s = ml & 1023;
                const size_t idx = (((size_t)(bb * HD + h) * SD + s) * DK + d);
                const float v0 = tot[fm][fn][rr * 2 + 0] + b0;
                const float v1 = tot[fm][fn][rr * 2 + 1] + b1;
                if (p == 2) {
                    *(float2*)(g_v + idx) = make_float2(v0, v1);
                } else {
                    unsigned short x0, x1, y0, y1;
                    split2(v0, x0, x1);
                    split2(v1, y0, y1);
                    *(uint32_t*)(o0 + idx) = (uint32_t)x0 | ((uint32_t)y0 << 16);
                    *(uint32_t*)(o1 + idx) = (uint32_t)x1 | ((uint32_t)y1 << 16);
                }
            }
        }
    }
}

// =====================================================================
// Kernel: Vsum[bh][d] = sum_s v[bh][s][d]
// =====================================================================
__global__ __launch_bounds__(256) void vsum_kernel()
{
    __shared__ float red[4][64];
    const int bh = blockIdx.x;
    const int d  = threadIdx.x & 63;
    const int c  = threadIdx.x >> 6;
    const float* vp = g_v + (size_t)bh * SD * DK + (size_t)c * 256 * DK + d;
    float s = 0.0f;
#pragma unroll 8
    for (int i = 0; i < 256; i++) s += vp[i * DK];
    red[c][d] = s;
    __syncthreads();
    if (c == 0) g_vsum[bh * DK + d] = red[0][d] + red[1][d] + red[2][d] + red[3][d];
}

// =====================================================================
// Attention: fp16 2-term mma.sync scores (cp.async 64-row k chunks,
// chunk-level accumulators: main chain 4, cross chain 8) + top-32 + context.
// Score rows padded to 1028 floats (bank-conflict fix).
// =====================================================================
#define SCW    1028                     // padded score row stride (floats)
#define A_SC   0                        // 16*1028*4 = 65792
#define A_Q0   65792                    // 16*144 = 2304 each
#define A_Q1   (A_Q0 + 2304)
#define A_KS   (A_Q1 + 2304)            // 2 stages * 2 terms * 64*144 = 36864
#define A_TI   (A_KS + 36864)           // 2048
#define A_TW   (A_TI + 2048)
#define ATT_SMEM_BYTES (A_TW + 2048)    // 111360

__global__ __launch_bounds__(256, 2) void attn_kernel(float* __restrict__ out)
{
    extern __shared__ char smc[];
    const uint32_t sb = smem_u32(smc);

    const int bh  = blockIdx.y;
    const int q0  = blockIdx.x * 16;
    const int tid = threadIdx.x;
    const int w   = tid >> 5;
    const int lane = tid & 31;

    // ---- load q tile 2-term: [16][64] -> [16][72] padded ----
    {
        const int arr = tid >> 7;            // 0,1
        const int row = (tid & 127) >> 3;
        const int grp = tid & 7;
        const unsigned short* src = ((arr == 0) ? g_q0 : g_q1)
                                    + ((size_t)bh * SD + q0 + row) * DK + grp * 8;
        *(uint4*)(smc + A_Q0 + arr * 2304 + row * 144 + grp * 16) = *(const uint4*)src;
    }

    const uint32_t a_l = (uint32_t)((((lane >> 3) & 1) * 8 + (lane & 7)) * 144 + (lane >> 4) * 16);
    const int l16 = lane & 15;
    const uint32_t b_l2 = (uint32_t)((l16 & 7) * 144 + (l16 >> 3) * 16);

    // ---- k chunk cp.async issue: 64 rows x 128B x 2 terms ----
    const int krow = tid >> 2;     // 0..63
    const int kq   = tid & 3;
    auto kissue = [&](int ch) {
        const uint32_t dst = sb + A_KS + (ch & 1) * 18432 + (uint32_t)(krow * 144 + kq * 32);
        const size_t src = ((size_t)bh * SD + ch * 64 + krow) * DK + kq * 16;
        cp_async16(dst, g_k0 + src);           cp_async16(dst + 16, g_k0 + src + 8);
        cp_async16(dst + 9216, g_k1 + src);    cp_async16(dst + 9216 + 16, g_k1 + src + 8);
    };

    kissue(0); CP_COMMIT();
    __syncthreads();   // q tile visible

    // hoist q fragments (constant across chunks)
    uint32_t qf0[4][4], qf1[4][4];
#pragma unroll
    for (int ks = 0; ks < 4; ks++) {
        ldmx4(sb + A_Q0 + a_l + ks * 32, qf0[ks]);
        ldmx4(sb + A_Q1 + a_l + ks * 32, qf1[ks]);
    }

    // ---- Phase 1: scores[16][1024], 16 chunks of 64 k-rows ----
    for (int ch = 0; ch < 16; ch++) {
        if (ch < 15) { kissue(ch + 1); CP_COMMIT(); cp_wait<1>(); }
        else         { cp_wait<0>(); }
        __syncthreads();

        const uint32_t kbase = sb + A_KS + (ch & 1) * 18432 + (uint32_t)((w * 8) * 144);
        float mA[4], cr[4];
        {   // ks = 0: zero-init accumulators through mma
            uint32_t k0f[2], k1f[2];
            ldmx2(kbase + b_l2, k0f);
            ldmx2(kbase + 9216 + b_l2, k1f);
            mma16816_zi(mA, qf0[0], k0f);
            mma16816_zi(cr, qf0[0], k1f);
            mma16816(cr, qf1[0], k0f);
        }
#pragma unroll
        for (int ks = 1; ks < 4; ks++) {
            uint32_t k0f[2], k1f[2];
            ldmx2(kbase + b_l2 + ks * 32, k0f);
            ldmx2(kbase + 9216 + b_l2 + ks * 32, k1f);
            mma16816(mA, qf0[ks], k0f);   // main chain (len 4)
            mma16816(cr, qf0[ks], k1f);   // cross chain (len 8)
            mma16816(cr, qf1[ks], k0f);
        }
        {
            const int col = ch * 64 + w * 8 + (lane & 3) * 2;
            const int r1 = lane >> 2;
            *(float2*)(smc + A_SC + ((size_t)r1 * SCW + col) * 4)
                = make_float2(mA[0] + cr[0], mA[1] + cr[1]);
            *(float2*)(smc + A_SC + ((size_t)(r1 + 8) * SCW + col) * 4)
                = make_float2(mA[2] + cr[2], mA[3] + cr[3]);
        }
        __syncthreads();
    }

    // ---- Phase 2+3: per warp, 2 rows: exact top-32 + context ----
    float (*sc)[SCW]   = (float(*)[SCW])(smc + A_SC);
    int   (*top_i)[32] = (int(*)[32])(smc + A_TI);
    float (*top_w)[32] = (float(*)[32])(smc + A_TW);

    const unsigned lmask_lt = (1u << lane) - 1u;
    const int bb = bh >> 4;
    const int h  = bh & 15;
    const float* vptr = g_v + (size_t)bh * SD * DK;

    for (int rr = 0; rr < 2; rr++) {
        const int row = w * 2 + rr;

        unsigned key[32];
#pragma unroll
        for (int i = 0; i < 32; i++) {
            float s = sc[row][lane + 32 * i] * 0.125f;
            unsigned ub = __float_as_uint(s);
            key[i] = (ub & 0x80000000u) ? ~ub : (ub | 0x80000000u);
        }

        unsigned T = 0u;
        bool done = false;
        for (int bit = 31; bit >= 0 && !done; --bit) {
            unsigned cand = T | (1u << bit);
            int c = 0;
#pragma unroll
            for (int i = 0; i < 32; i++) c += (key[i] >= cand) ? 1 : 0;
#pragma unroll
            for (int o = 16; o > 0; o >>= 1) c += __shfl_xor_sync(0xffffffffu, c, o);
            if (c >= TOPK) { T = cand; if (c == TOPK) done = true; }
        }

        int base = 0;
#pragma unroll
        for (int i = 0; i < 32; i++) {
            bool sel = key[i] > T;
            unsigned m = __ballot_sync(0xffffffffu, sel);
            if (sel) {
                int pos = base + __popc(m & lmask_lt);
                unsigned ub = (key[i] & 0x80000000u) ? (key[i] & 0x7fffffffu) : ~key[i];
                top_i[row][pos] = lane + 32 * i;
                top_w[row][pos] = __expf(__uint_as_float(ub));
            }
            base += __popc(m);
        }
        for (int i = 0; i < 32 && base < TOPK; i++) {
            bool sel = (key[i] == T);
            unsigned m = __ballot_sync(0xffffffffu, sel);
            if (sel) {
                int pos = base + __popc(m & lmask_lt);
                if (pos < TOPK) {
                    unsigned ub = (key[i] & 0x80000000u) ? (key[i] & 0x7fffffffu) : ~key[i];
                    top_i[row][pos] = lane + 32 * i;
                    top_w[row][pos] = __expf(__uint_as_float(ub));
                }
            }
            base += __popc(m);
        }
        __syncwarp();

        float wsum = top_w[row][lane];
#pragma unroll
        for (int o = 16; o > 0; o >>= 1) wsum += __shfl_xor_sync(0xffffffffu, wsum, o);
        float rden = 1.0f / ((float)(SD - TOPK) + wsum + 1e-8f);

        float a0 = g_vsum[bh * DK + lane * 2];
        float a1 = g_vsum[bh * DK + lane * 2 + 1];
#pragma unroll
        for (int t = 0; t < TOPK; t++) {
            int   idx = top_i[row][t];
            float wv  = top_w[row][t] - 1.0f;
            float2 vv = *(const float2*)(vptr + (size_t)idx * DK + lane * 2);
            a0 = fmaf(wv, vv.x, a0);
            a1 = fmaf(wv, vv.y, a1);
        }
        const int s_glob = q0 + row;
        *(float2*)(out + ((size_t)(bb * SD + s_glob) * DM) + h * DK + lane * 2)
            = make_float2(a0 * rden, a1 * rden);
    }
}

// =====================================================================
extern "C" void kernel_launch(void* const* d_in, const int* in_sizes, int n_in,
                              void* d_out, int out_size)
{
    (void)in_sizes; (void)n_in; (void)out_size;
    const float* Q  = (const float*)d_in[0];
    const float* K  = (const float*)d_in[1];
    const float* V  = (const float*)d_in[2];
    const float* Wq = (const float*)d_in[3];
    const float* bq = (const float*)d_in[4];
    const float* Wk = (const float*)d_in[5];
    const float* bk = (const float*)d_in[6];
    const float* Wv = (const float*)d_in[7];
    const float* bv = (const float*)d_in[8];
    float* out = (float*)d_out;

    cudaFuncSetAttribute(proj_mma_kernel, cudaFuncAttributeMaxDynamicSharedMemorySize, PROJ_SMEM);
    cudaFuncSetAttribute(attn_kernel, cudaFuncAttributeMaxDynamicSharedMemorySize, ATT_SMEM_BYTES);

    convert_all_kernel<<<27648, 256>>>(Q, K, V, Wq, Wk, Wv);
    proj_mma_kernel<<<dim3(8, 192), 256, PROJ_SMEM>>>(bq, bk, bv);
    vsum_kernel<<<BD * HD, 256>>>();
    attn_kernel<<<dim3(SD / 16, BD * HD), 256, ATT_SMEM_BYTES>>>(out);
}